// round 2
// baseline (speedup 1.0000x reference)
#include <cuda_runtime.h>
#include <cuda_bf16.h>
#include <math.h>

// ---------------------------------------------------------------------------
// PCENetwork: patch-conditional experts, 2 layers + pool + classifier
// B=16, H=W=208
// Layer0: ps=16 (13x13=169 patches), Cin=3, E=8, Cout=8, then 1x1 fc 8->8
// Layer1: ps=13 (16x16=256 patches), Cin=8, E=8, Cout=16, then 1x1 fc 16->16
// Pool: 26x26 mean = 2x2 layer-1 patches -> fuse fc1+pool into layer1 kernel
// Classifier: [16,1024] @ [100,1024]^T + b
// ---------------------------------------------------------------------------

#define BATCH 16
#define HW 208

// scratch (device globals; no allocation allowed)
__device__ float g_x1[BATCH * 8 * HW * HW];      // layer0 output (after fc0)
__device__ float g_scores0[169 * 8];
__device__ float g_scores1[256 * 8];
__device__ float g_A0[8 * 20];
__device__ float g_c0[8];
__device__ float g_A1[8 * 20];
__device__ float g_c1[8];
__device__ float g_pooled[BATCH * 16 * 8 * 8];   // [b][c][8][8]

// ---------------------------------------------------------------------------
// Router prep: collapse proj(128x20) and keys(8x128) into A(8x20), c(8)
// ---------------------------------------------------------------------------
__global__ void prep_kernel(const float* __restrict__ pw0, const float* __restrict__ pb0,
                            const float* __restrict__ k0,
                            const float* __restrict__ pw1, const float* __restrict__ pb1,
                            const float* __restrict__ k1) {
    int tid = blockIdx.x * blockDim.x + threadIdx.x;
    if (tid < 160) {
        int e = tid / 20, c = tid % 20;
        float v = 0.f;
        for (int d = 0; d < 128; d++) v += k0[e * 128 + d] * pw0[d * 20 + c];
        g_A0[tid] = v;
    } else if (tid < 168) {
        int e = tid - 160;
        float v = 0.f;
        for (int d = 0; d < 128; d++) v += k0[e * 128 + d] * pb0[d];
        g_c0[e] = v;
    } else if (tid < 328) {
        int t = tid - 168;
        int e = t / 20, c = t % 20;
        float v = 0.f;
        for (int d = 0; d < 128; d++) v += k1[e * 128 + d] * pw1[d * 20 + c];
        g_A1[t] = v;
    } else if (tid < 336) {
        int e = tid - 328;
        float v = 0.f;
        for (int d = 0; d < 128; d++) v += k1[e * 128 + d] * pb1[d];
        g_c1[e] = v;
    }
}

// ---------------------------------------------------------------------------
// Router scores: per patch, mean of 20 Fourier coord channels -> logits ->
// softmax -> threshold(1/16) -> renorm. Templated on layer so no host-side
// symbol-address lookups are needed.
// ---------------------------------------------------------------------------
template <int LAYER>
__global__ void router_kernel(int ps, int gw) {
    const float* A  = (LAYER == 0) ? g_A0 : g_A1;
    const float* cb = (LAYER == 0) ? g_c0 : g_c1;
    float* scores   = (LAYER == 0) ? g_scores0 : g_scores1;

    int p = blockIdx.x;
    int ph = p / gw, pw = p % gw;
    __shared__ float s_phi[20];
    int tid = threadIdx.x;
    if (tid < 20) s_phi[tid] = 0.f;
    __syncthreads();

    float loc[20];
#pragma unroll
    for (int i = 0; i < 20; i++) loc[i] = 0.f;

    const float PI = 3.14159265358979323846f;
    int n = ps * ps;
    for (int i = tid; i < n; i += blockDim.x) {
        int y = i / ps, x = i % ps;
        int gy = ph * ps + y, gx = pw * ps + x;
        float yy = (2.0f * (float)gy) / 207.0f - 1.0f;
        float xx = (2.0f * (float)gx) / 207.0f - 1.0f;
        float r = sqrtf(xx * xx + yy * yy);
        float a = atan2f(yy, xx);
        loc[0] += xx; loc[1] += yy; loc[2] += r; loc[3] += a;
        float base[4] = {xx, yy, r, a};
        int c = 4;
#pragma unroll
        for (int f = 1; f <= 2; f++) {
            float w = (f == 1 ? 2.0f : 4.0f) * PI;
#pragma unroll
            for (int bb = 0; bb < 4; bb++) {
                float sv, cv;
                sincosf(w * base[bb], &sv, &cv);
                loc[c++] += sv;
                loc[c++] += cv;
            }
        }
    }
#pragma unroll
    for (int k = 0; k < 20; k++) {
        float v = loc[k];
#pragma unroll
        for (int off = 16; off; off >>= 1) v += __shfl_down_sync(0xffffffffu, v, off);
        if ((tid & 31) == 0) atomicAdd(&s_phi[k], v);
    }
    __syncthreads();
    if (tid == 0) {
        float inv = 1.0f / (float)n;
        float logit[8];
        float mx = -1e30f;
#pragma unroll
        for (int e = 0; e < 8; e++) {
            float v = cb[e];
            for (int c = 0; c < 20; c++) v += A[e * 20 + c] * (s_phi[c] * inv);
            logit[e] = v;
            mx = fmaxf(mx, v);
        }
        float sum = 0.f;
#pragma unroll
        for (int e = 0; e < 8; e++) { logit[e] = expf(logit[e] - mx); sum += logit[e]; }
        float s2 = 0.f;
#pragma unroll
        for (int e = 0; e < 8; e++) {
            float sc = logit[e] / sum;
            sc = (sc > 0.0625f) ? sc : 0.f;
            logit[e] = sc;
            s2 += sc;
        }
        float inv2 = 1.0f / (s2 + 1e-6f);
#pragma unroll
        for (int e = 0; e < 8; e++) scores[p * 8 + e] = logit[e] * inv2;
    }
}

// ---------------------------------------------------------------------------
// Layer 0: per-patch expert conv (16x16 patch, pad-1 inside patch),
// gated combine, fused fc0 1x1 (8->8), write NCHW image to g_x1.
// One block per (b, patch). 256 threads = one pixel each.
// ---------------------------------------------------------------------------
__global__ void layer0_kernel(const float* __restrict__ X, const float* __restrict__ w_exp,
                              const float* __restrict__ b_exp, const float* __restrict__ w_fc,
                              const float* __restrict__ b_fc) {
    int bp = blockIdx.x;
    int b = bp / 169, p = bp % 169;
    int ph = p / 13, pw = p % 13;

    __shared__ float s_w[8 * 8 * 3 * 9];     // 1728
    __shared__ float s_tile[3][18][18];
    __shared__ float s_b[64], s_fc[64], s_bfc[8], s_sc[8];

    int tid = threadIdx.x;
    for (int i = tid; i < 1728; i += 256) s_w[i] = w_exp[i];
    if (tid < 64) { s_b[tid] = b_exp[tid]; s_fc[tid] = w_fc[tid]; }
    if (tid < 8) { s_bfc[tid] = b_fc[tid]; s_sc[tid] = g_scores0[p * 8 + tid]; }
    for (int i = tid; i < 3 * 18 * 18; i += 256) ((float*)s_tile)[i] = 0.f;
    __syncthreads();

    int y0 = ph * 16, x0 = pw * 16;
    for (int i = tid; i < 3 * 256; i += 256) {
        int c = i >> 8, r = i & 255;
        int y = r >> 4, x = r & 15;
        s_tile[c][y + 1][x + 1] = X[((b * 3 + c) * HW + y0 + y) * HW + x0 + x];
    }
    __syncthreads();

    int y = tid >> 4, x = tid & 15;
    float comb[8];
#pragma unroll
    for (int k = 0; k < 8; k++) comb[k] = 0.f;

    for (int e = 0; e < 8; e++) {
        float s = s_sc[e];
        if (s == 0.f) continue;
        float acc[8];
#pragma unroll
        for (int oc = 0; oc < 8; oc++) acc[oc] = s_b[e * 8 + oc];
#pragma unroll
        for (int ic = 0; ic < 3; ic++) {
            float t[9];
#pragma unroll
            for (int ky = 0; ky < 3; ky++)
#pragma unroll
                for (int kx = 0; kx < 3; kx++)
                    t[ky * 3 + kx] = s_tile[ic][y + ky][x + kx];
#pragma unroll
            for (int oc = 0; oc < 8; oc++) {
                const float* w = &s_w[((e * 8 + oc) * 3 + ic) * 9];
#pragma unroll
                for (int k = 0; k < 9; k++) acc[oc] += w[k] * t[k];
            }
        }
#pragma unroll
        for (int oc = 0; oc < 8; oc++) comb[oc] += s * fmaxf(acc[oc], 0.f);
    }

    // fc0 (1x1, 8->8) and store NCHW
    int gy = y0 + y, gx = x0 + x;
#pragma unroll
    for (int c = 0; c < 8; c++) {
        float v = s_bfc[c];
#pragma unroll
        for (int k = 0; k < 8; k++) v += s_fc[c * 8 + k] * comb[k];
        g_x1[((b * 8 + c) * HW + gy) * HW + gx] = v;
    }
}

// ---------------------------------------------------------------------------
// Layer 1 fused with fc1 + 26x26 avg pool.
// One block per (b, patch). Patch = 13x13, 2x2 patches = one pool cell.
// Per patch: gated expert conv -> combined 16ch sums over pixels ->
// fc1 on the SUM (linear) -> atomicAdd into pooled accumulator.
// ---------------------------------------------------------------------------
__global__ void layer1_kernel(const float* __restrict__ w_exp, const float* __restrict__ b_exp,
                              const float* __restrict__ w_fc, const float* __restrict__ b_fc) {
    int bp = blockIdx.x;
    int b = bp >> 8, p = bp & 255;
    int ph = p >> 4, pw = p & 15;

    __shared__ float s_w[8 * 16 * 8 * 9];    // 9216 floats = 36 KB
    __shared__ float s_tile[8][15][15];      // 1800 floats
    __shared__ float s_b[128], s_sc[8], s_S[16], s_fc[256], s_bfc[16];

    int tid = threadIdx.x;
    for (int i = tid; i < 9216; i += 256) s_w[i] = w_exp[i];
    if (tid < 128) s_b[tid] = b_exp[tid];
    if (tid < 256) s_fc[tid] = w_fc[tid];
    if (tid < 16) { s_bfc[tid] = b_fc[tid]; s_S[tid] = 0.f; }
    if (tid < 8) s_sc[tid] = g_scores1[p * 8 + tid];
    for (int i = tid; i < 8 * 15 * 15; i += 256) ((float*)s_tile)[i] = 0.f;
    __syncthreads();

    int y0 = ph * 13, x0 = pw * 13;
    for (int i = tid; i < 8 * 169; i += 256) {
        int c = i / 169, r = i % 169;
        int y = r / 13, x = r % 13;
        s_tile[c][y + 1][x + 1] = g_x1[((b * 8 + c) * HW + y0 + y) * HW + x0 + x];
    }
    __syncthreads();

    float comb[16];
#pragma unroll
    for (int k = 0; k < 16; k++) comb[k] = 0.f;

    if (tid < 169) {
        int y = tid / 13, x = tid % 13;
        for (int e = 0; e < 8; e++) {
            float s = s_sc[e];
            if (s == 0.f) continue;
            float acc[16];
#pragma unroll
            for (int oc = 0; oc < 16; oc++) acc[oc] = s_b[e * 16 + oc];
#pragma unroll
            for (int ic = 0; ic < 8; ic++) {
                float t[9];
#pragma unroll
                for (int ky = 0; ky < 3; ky++)
#pragma unroll
                    for (int kx = 0; kx < 3; kx++)
                        t[ky * 3 + kx] = s_tile[ic][y + ky][x + kx];
#pragma unroll
                for (int oc = 0; oc < 16; oc++) {
                    const float* w = &s_w[((e * 16 + oc) * 8 + ic) * 9];
#pragma unroll
                    for (int k = 0; k < 9; k++) acc[oc] += w[k] * t[k];
                }
            }
#pragma unroll
            for (int oc = 0; oc < 16; oc++) comb[oc] += s * fmaxf(acc[oc], 0.f);
        }
    }

    // block reduce comb[16] over all threads (idle threads contribute 0)
#pragma unroll
    for (int k = 0; k < 16; k++) {
        float v = comb[k];
#pragma unroll
        for (int off = 16; off; off >>= 1) v += __shfl_down_sync(0xffffffffu, v, off);
        if ((tid & 31) == 0) atomicAdd(&s_S[k], v);
    }
    __syncthreads();

    if (tid < 16) {
        int c = tid;
        float v = 169.0f * s_bfc[c];
#pragma unroll
        for (int k = 0; k < 16; k++) v += s_fc[c * 16 + k] * s_S[k];
        // pool cell: (ph/2, pw/2); mean over 26*26 = 676 pixels
        atomicAdd(&g_pooled[((b * 16 + c) * 8 + (ph >> 1)) * 8 + (pw >> 1)], v * (1.0f / 676.0f));
    }
}

// ---------------------------------------------------------------------------
__global__ void zero_pooled_kernel() {
    int i = blockIdx.x * blockDim.x + threadIdx.x;
    if (i < BATCH * 16 * 64) g_pooled[i] = 0.f;
}

// ---------------------------------------------------------------------------
// Classifier: [16,1024] @ w_cls[100,1024]^T + b_cls -> [16,100]
// ---------------------------------------------------------------------------
__global__ void cls_kernel(const float* __restrict__ w, const float* __restrict__ bias,
                           float* __restrict__ out) {
    int b = blockIdx.x;
    __shared__ float s_p[1024];
    for (int i = threadIdx.x; i < 1024; i += blockDim.x) s_p[i] = g_pooled[b * 1024 + i];
    __syncthreads();
    for (int j = threadIdx.x; j < 100; j += blockDim.x) {
        float v = bias[j];
        const float* wr = &w[j * 1024];
        for (int k = 0; k < 1024; k++) v += wr[k] * s_p[k];
        out[b * 100 + j] = v;
    }
}

// ---------------------------------------------------------------------------
extern "C" void kernel_launch(void* const* d_in, const int* in_sizes, int n_in,
                              void* d_out, int out_size) {
    const float* X       = (const float*)d_in[0];
    const float* w_exp0  = (const float*)d_in[1];
    const float* b_exp0  = (const float*)d_in[2];
    const float* w_fc0   = (const float*)d_in[3];
    const float* b_fc0   = (const float*)d_in[4];
    const float* proj_w0 = (const float*)d_in[5];
    const float* proj_b0 = (const float*)d_in[6];
    const float* keys0   = (const float*)d_in[7];
    const float* w_exp1  = (const float*)d_in[8];
    const float* b_exp1  = (const float*)d_in[9];
    const float* w_fc1   = (const float*)d_in[10];
    const float* b_fc1   = (const float*)d_in[11];
    const float* proj_w1 = (const float*)d_in[12];
    const float* proj_b1 = (const float*)d_in[13];
    const float* keys1   = (const float*)d_in[14];
    const float* w_cls   = (const float*)d_in[15];
    const float* b_cls   = (const float*)d_in[16];
    float* out = (float*)d_out;

    prep_kernel<<<1, 512>>>(proj_w0, proj_b0, keys0, proj_w1, proj_b1, keys1);
    router_kernel<0><<<169, 256>>>(16, 13);
    router_kernel<1><<<256, 256>>>(13, 16);
    zero_pooled_kernel<<<(BATCH * 16 * 64 + 255) / 256, 256>>>();
    layer0_kernel<<<BATCH * 169, 256>>>(X, w_exp0, b_exp0, w_fc0, b_fc0);
    layer1_kernel<<<BATCH * 256, 256>>>(w_exp1, b_exp1, w_fc1, b_fc1);
    cls_kernel<<<BATCH, 128>>>(w_cls, b_cls, out);
}

// round 3
// speedup vs baseline: 1.0649x; 1.0649x over previous
#include <cuda_runtime.h>
#include <cuda_bf16.h>
#include <math.h>

// ---------------------------------------------------------------------------
// PCENetwork: patch-conditional experts, 2 layers + pool + classifier
// B=16, H=W=208
// Layer0: ps=16 (13x13=169 patches), Cin=3, E=8, Cout=8, then 1x1 fc 8->8
// Layer1: ps=13 (16x16=256 patches), Cin=8, E=8, Cout=16, then 1x1 fc 16->16
// Pool: 26x26 mean = 2x2 layer-1 patches -> block = pool cell, fc1+pool fused
// Classifier: [16,1024] @ [100,1024]^T + b
// ---------------------------------------------------------------------------

#define BATCH 16
#define HW 208

__device__ float g_x1[BATCH * 8 * HW * HW];      // layer0 output (after fc0)
__device__ float g_scores0[169 * 8];
__device__ float g_scores1[256 * 8];
__device__ float g_A0[8 * 20];
__device__ float g_c0[8];
__device__ float g_A1[8 * 20];
__device__ float g_c1[8];
__device__ float g_pooled[BATCH * 16 * 8 * 8];   // [b][c][8][8]

// ---------------------------------------------------------------------------
// Router prep: collapse proj(128x20) and keys(8x128) into A(8x20), c(8)
// ---------------------------------------------------------------------------
__global__ void prep_kernel(const float* __restrict__ pw0, const float* __restrict__ pb0,
                            const float* __restrict__ k0,
                            const float* __restrict__ pw1, const float* __restrict__ pb1,
                            const float* __restrict__ k1) {
    int tid = blockIdx.x * blockDim.x + threadIdx.x;
    if (tid < 160) {
        int e = tid / 20, c = tid % 20;
        float v = 0.f;
        for (int d = 0; d < 128; d++) v += k0[e * 128 + d] * pw0[d * 20 + c];
        g_A0[tid] = v;
    } else if (tid < 168) {
        int e = tid - 160;
        float v = 0.f;
        for (int d = 0; d < 128; d++) v += k0[e * 128 + d] * pb0[d];
        g_c0[e] = v;
    } else if (tid < 328) {
        int t = tid - 168;
        int e = t / 20, c = t % 20;
        float v = 0.f;
        for (int d = 0; d < 128; d++) v += k1[e * 128 + d] * pw1[d * 20 + c];
        g_A1[t] = v;
    } else if (tid < 336) {
        int e = tid - 328;
        float v = 0.f;
        for (int d = 0; d < 128; d++) v += k1[e * 128 + d] * pb1[d];
        g_c1[e] = v;
    }
}

// ---------------------------------------------------------------------------
// Router: per-patch mean of 20 Fourier channels -> logits -> softmax ->
// threshold(1/16) -> renorm.
// ---------------------------------------------------------------------------
template <int LAYER>
__global__ void router_kernel(int ps, int gw) {
    const float* A  = (LAYER == 0) ? g_A0 : g_A1;
    const float* cb = (LAYER == 0) ? g_c0 : g_c1;
    float* scores   = (LAYER == 0) ? g_scores0 : g_scores1;

    int p = blockIdx.x;
    int ph = p / gw, pw = p % gw;
    __shared__ float s_phi[20];
    int tid = threadIdx.x;
    if (tid < 20) s_phi[tid] = 0.f;
    __syncthreads();

    float loc[20];
#pragma unroll
    for (int i = 0; i < 20; i++) loc[i] = 0.f;

    const float PI = 3.14159265358979323846f;
    int n = ps * ps;
    for (int i = tid; i < n; i += blockDim.x) {
        int y = i / ps, x = i % ps;
        int gy = ph * ps + y, gx = pw * ps + x;
        float yy = (2.0f * (float)gy) / 207.0f - 1.0f;
        float xx = (2.0f * (float)gx) / 207.0f - 1.0f;
        float r = sqrtf(xx * xx + yy * yy);
        float a = atan2f(yy, xx);
        loc[0] += xx; loc[1] += yy; loc[2] += r; loc[3] += a;
        float base[4] = {xx, yy, r, a};
        int c = 4;
#pragma unroll
        for (int f = 1; f <= 2; f++) {
            float w = (f == 1 ? 2.0f : 4.0f) * PI;
#pragma unroll
            for (int bb = 0; bb < 4; bb++) {
                float sv, cv;
                sincosf(w * base[bb], &sv, &cv);
                loc[c++] += sv;
                loc[c++] += cv;
            }
        }
    }
#pragma unroll
    for (int k = 0; k < 20; k++) {
        float v = loc[k];
#pragma unroll
        for (int off = 16; off; off >>= 1) v += __shfl_down_sync(0xffffffffu, v, off);
        if ((tid & 31) == 0) atomicAdd(&s_phi[k], v);
    }
    __syncthreads();
    if (tid == 0) {
        float inv = 1.0f / (float)n;
        float logit[8];
        float mx = -1e30f;
#pragma unroll
        for (int e = 0; e < 8; e++) {
            float v = cb[e];
            for (int c = 0; c < 20; c++) v += A[e * 20 + c] * (s_phi[c] * inv);
            logit[e] = v;
            mx = fmaxf(mx, v);
        }
        float sum = 0.f;
#pragma unroll
        for (int e = 0; e < 8; e++) { logit[e] = expf(logit[e] - mx); sum += logit[e]; }
        float s2 = 0.f;
#pragma unroll
        for (int e = 0; e < 8; e++) {
            float sc = logit[e] / sum;
            sc = (sc > 0.0625f) ? sc : 0.f;
            logit[e] = sc;
            s2 += sc;
        }
        float inv2 = 1.0f / (s2 + 1e-6f);
#pragma unroll
        for (int e = 0; e < 8; e++) scores[p * 8 + e] = logit[e] * inv2;
    }
}

// ---------------------------------------------------------------------------
// Layer 0: block per (b,patch); 64 threads = (ocGroup 0..3) x (row 0..15).
// Each thread computes a 16-pixel row for 2 output channels with weights in
// registers (amortized over the row). fc0 fused via smem staging.
// ---------------------------------------------------------------------------
__global__ __launch_bounds__(64) void layer0_kernel(
        const float* __restrict__ X, const float* __restrict__ w_exp,
        const float* __restrict__ b_exp, const float* __restrict__ w_fc,
        const float* __restrict__ b_fc) {
    int bp = blockIdx.x;
    int b = bp / 169, p = bp % 169;
    int ph = p / 13, pw = p % 13;

    __shared__ float s_w[8 * 8 * 3 * 9];     // 1728 floats
    __shared__ float s_tile[3][18][18];
    __shared__ float s_comb[8][16][16];      // 8 KB staging for fc0
    __shared__ float s_b[64], s_fc[64], s_bfc[8], s_sc[8];

    int tid = threadIdx.x;
    for (int i = tid; i < 1728; i += 64) s_w[i] = w_exp[i];
    if (tid < 64) { s_b[tid] = b_exp[tid]; s_fc[tid] = w_fc[tid]; }
    if (tid < 8) { s_bfc[tid] = b_fc[tid]; s_sc[tid] = g_scores0[p * 8 + tid]; }
    for (int i = tid; i < 3 * 18 * 18; i += 64) ((float*)s_tile)[i] = 0.f;
    __syncthreads();

    int y0 = ph * 16, x0 = pw * 16;
    for (int i = tid; i < 3 * 256; i += 64) {
        int c = i >> 8, r = i & 255;
        int y = r >> 4, x = r & 15;
        s_tile[c][y + 1][x + 1] = X[((b * 3 + c) * HW + y0 + y) * HW + x0 + x];
    }
    __syncthreads();

    int row = tid & 15;      // output row within patch
    int ocg = tid >> 4;      // 0..3, handles oc = 2*ocg, 2*ocg+1

    float comb[2][16];
#pragma unroll
    for (int o = 0; o < 2; o++)
#pragma unroll
        for (int px = 0; px < 16; px++) comb[o][px] = 0.f;

    for (int e = 0; e < 8; e++) {
        float s = s_sc[e];
        if (s == 0.f) continue;
        float acc[2][16];
#pragma unroll
        for (int o = 0; o < 2; o++) {
            float bb = s_b[e * 8 + ocg * 2 + o];
#pragma unroll
            for (int px = 0; px < 16; px++) acc[o][px] = bb;
        }
#pragma unroll
        for (int ic = 0; ic < 3; ic++) {
            float t0[18], t1[18], t2[18];
#pragma unroll
            for (int j = 0; j < 18; j++) {
                t0[j] = s_tile[ic][row + 0][j];
                t1[j] = s_tile[ic][row + 1][j];
                t2[j] = s_tile[ic][row + 2][j];
            }
#pragma unroll
            for (int o = 0; o < 2; o++) {
                const float* wp = &s_w[((e * 8 + ocg * 2 + o) * 3 + ic) * 9];
                float w0 = wp[0], w1 = wp[1], w2 = wp[2];
                float w3 = wp[3], w4 = wp[4], w5 = wp[5];
                float w6 = wp[6], w7 = wp[7], w8 = wp[8];
#pragma unroll
                for (int px = 0; px < 16; px++) {
                    float v = acc[o][px];
                    v += w0 * t0[px] + w1 * t0[px + 1] + w2 * t0[px + 2];
                    v += w3 * t1[px] + w4 * t1[px + 1] + w5 * t1[px + 2];
                    v += w6 * t2[px] + w7 * t2[px + 1] + w8 * t2[px + 2];
                    acc[o][px] = v;
                }
            }
        }
#pragma unroll
        for (int o = 0; o < 2; o++)
#pragma unroll
            for (int px = 0; px < 16; px++)
                comb[o][px] += s * fmaxf(acc[o][px], 0.f);
    }

#pragma unroll
    for (int o = 0; o < 2; o++)
#pragma unroll
        for (int px = 0; px < 16; px++)
            s_comb[ocg * 2 + o][row][px] = comb[o][px];
    __syncthreads();

    // fc0 (1x1, 8->8): thread handles 4 consecutive pixels -> float4 stores
    {
        int i0 = tid * 4;
        int y = i0 >> 4, xb = i0 & 15;       // 4 pixels same row
        float cv[8][4];
#pragma unroll
        for (int k = 0; k < 8; k++)
#pragma unroll
            for (int j = 0; j < 4; j++) cv[k][j] = s_comb[k][y][xb + j];
        int gy = y0 + y, gx = x0 + xb;
#pragma unroll
        for (int c = 0; c < 8; c++) {
            float4 out;
            float* po = (float*)&out;
#pragma unroll
            for (int j = 0; j < 4; j++) {
                float v = s_bfc[c];
#pragma unroll
                for (int k = 0; k < 8; k++) v += s_fc[c * 8 + k] * cv[k][j];
                po[j] = v;
            }
            *(float4*)&g_x1[((size_t)(b * 8 + c) * HW + gy) * HW + gx] = out;
        }
    }
}

// ---------------------------------------------------------------------------
// Layer 1 + fc1 + 26x26 pool. Block per (b, pool cell) = 4 patches (2x2).
// 256 threads; active thread = (patch q 0..3, ocGroup 0..3, row 0..12):
// 13-pixel row x 4 output channels, weights in registers per (e,ic).
// Only channel SUMS are needed (fc1 and pool are linear over pixels), so
// per-pixel outputs are never materialized. Writes g_pooled directly.
// ---------------------------------------------------------------------------
__global__ __launch_bounds__(256) void layer1_kernel(
        const float* __restrict__ w_exp, const float* __restrict__ b_exp,
        const float* __restrict__ w_fc, const float* __restrict__ b_fc) {
    extern __shared__ float dyn[];
    float* s_w = dyn;                        // 9216 floats (36 KB)
    float* s_tile = dyn + 9216;              // 4 * 8 * 15 * 15 = 7200 floats

    __shared__ float s_b[128], s_fc[256], s_bfc[16];
    __shared__ float s_sc[4][8];
    __shared__ float s_S[4][16];

    int bp = blockIdx.x;
    int b = bp >> 6, cell = bp & 63;
    int cy = cell >> 3, cx = cell & 7;

    int tid = threadIdx.x;
    for (int i = tid; i < 9216; i += 256) s_w[i] = w_exp[i];
    if (tid < 128) s_b[tid] = b_exp[tid];
    if (tid < 256) s_fc[tid] = w_fc[tid];
    if (tid < 16) s_bfc[tid] = b_fc[tid];
    if (tid < 64) ((float*)s_S)[tid] = 0.f;
    if (tid < 32) {
        int q = tid >> 3, e = tid & 7;
        int php = 2 * cy + (q >> 1), pwp = 2 * cx + (q & 1);
        s_sc[q][e] = g_scores1[(php * 16 + pwp) * 8 + e];
    }
    for (int i = tid; i < 7200; i += 256) s_tile[i] = 0.f;
    __syncthreads();

    // load 4 patch tiles (13x13 interior of 15x15 padded)
    for (int i = tid; i < 4 * 8 * 169; i += 256) {
        int q = i / 1352, r = i % 1352;
        int c = r / 169, rr = r % 169;
        int y = rr / 13, x = rr % 13;
        int php = 2 * cy + (q >> 1), pwp = 2 * cx + (q & 1);
        s_tile[((q * 8 + c) * 15 + y + 1) * 15 + x + 1] =
            g_x1[((size_t)(b * 8 + c) * HW + php * 13 + y) * HW + pwp * 13 + x];
    }
    __syncthreads();

    if (tid < 208) {
        int q = tid / 52;
        int r = tid % 52;
        int ocg = r / 13;      // 0..3, handles oc = 4*ocg .. 4*ocg+3
        int row = r % 13;

        float sums[4];
#pragma unroll
        for (int o = 0; o < 4; o++) sums[o] = 0.f;

        for (int e = 0; e < 8; e++) {
            float s = s_sc[q][e];
            if (s == 0.f) continue;
            float acc[4][13];
#pragma unroll
            for (int o = 0; o < 4; o++) {
                float bb = s_b[e * 16 + ocg * 4 + o];
#pragma unroll
                for (int px = 0; px < 13; px++) acc[o][px] = bb;
            }
#pragma unroll
            for (int ic = 0; ic < 8; ic++) {
                const float* tb = &s_tile[((q * 8 + ic) * 15 + row) * 15];
                float t0[15], t1[15], t2[15];
#pragma unroll
                for (int j = 0; j < 15; j++) {
                    t0[j] = tb[j];
                    t1[j] = tb[15 + j];
                    t2[j] = tb[30 + j];
                }
#pragma unroll
                for (int o = 0; o < 4; o++) {
                    const float* wp = &s_w[((e * 16 + ocg * 4 + o) * 8 + ic) * 9];
                    float w0 = wp[0], w1 = wp[1], w2 = wp[2];
                    float w3 = wp[3], w4 = wp[4], w5 = wp[5];
                    float w6 = wp[6], w7 = wp[7], w8 = wp[8];
#pragma unroll
                    for (int px = 0; px < 13; px++) {
                        float v = acc[o][px];
                        v += w0 * t0[px] + w1 * t0[px + 1] + w2 * t0[px + 2];
                        v += w3 * t1[px] + w4 * t1[px + 1] + w5 * t1[px + 2];
                        v += w6 * t2[px] + w7 * t2[px + 1] + w8 * t2[px + 2];
                        acc[o][px] = v;
                    }
                }
            }
#pragma unroll
            for (int o = 0; o < 4; o++) {
                float rs = 0.f;
#pragma unroll
                for (int px = 0; px < 13; px++) rs += fmaxf(acc[o][px], 0.f);
                sums[o] += s * rs;
            }
        }
#pragma unroll
        for (int o = 0; o < 4; o++)
            atomicAdd(&s_S[q][ocg * 4 + o], sums[o]);
    }
    __syncthreads();

    // fc1 on the cell-wide channel sums + pool normalization
    if (tid < 16) {
        int c = tid;
        float v = 676.0f * s_bfc[c];
#pragma unroll
        for (int k = 0; k < 16; k++) {
            float Ssum = s_S[0][k] + s_S[1][k] + s_S[2][k] + s_S[3][k];
            v += s_fc[c * 16 + k] * Ssum;
        }
        g_pooled[((b * 16 + c) * 8 + cy) * 8 + cx] = v * (1.0f / 676.0f);
    }
}

// ---------------------------------------------------------------------------
// Classifier: [16,1024] @ w_cls[100,1024]^T + b_cls -> [16,100]
// ---------------------------------------------------------------------------
__global__ void cls_kernel(const float* __restrict__ w, const float* __restrict__ bias,
                           float* __restrict__ out) {
    int b = blockIdx.x;
    __shared__ float s_p[1024];
    for (int i = threadIdx.x; i < 1024; i += blockDim.x) s_p[i] = g_pooled[b * 1024 + i];
    __syncthreads();
    for (int j = threadIdx.x; j < 100; j += blockDim.x) {
        float v = bias[j];
        const float* wr = &w[j * 1024];
        for (int k = 0; k < 1024; k++) v += wr[k] * s_p[k];
        out[b * 100 + j] = v;
    }
}

// ---------------------------------------------------------------------------
extern "C" void kernel_launch(void* const* d_in, const int* in_sizes, int n_in,
                              void* d_out, int out_size) {
    const float* X       = (const float*)d_in[0];
    const float* w_exp0  = (const float*)d_in[1];
    const float* b_exp0  = (const float*)d_in[2];
    const float* w_fc0   = (const float*)d_in[3];
    const float* b_fc0   = (const float*)d_in[4];
    const float* proj_w0 = (const float*)d_in[5];
    const float* proj_b0 = (const float*)d_in[6];
    const float* keys0   = (const float*)d_in[7];
    const float* w_exp1  = (const float*)d_in[8];
    const float* b_exp1  = (const float*)d_in[9];
    const float* w_fc1   = (const float*)d_in[10];
    const float* b_fc1   = (const float*)d_in[11];
    const float* proj_w1 = (const float*)d_in[12];
    const float* proj_b1 = (const float*)d_in[13];
    const float* keys1   = (const float*)d_in[14];
    const float* w_cls   = (const float*)d_in[15];
    const float* b_cls   = (const float*)d_in[16];
    float* out = (float*)d_out;

    const int DYN1 = (9216 + 7200) * sizeof(float);   // 65,664 bytes
    static int configured = 0;
    if (!configured) {
        cudaFuncSetAttribute(layer1_kernel, cudaFuncAttributeMaxDynamicSharedMemorySize, DYN1);
        configured = 1;
    }

    prep_kernel<<<1, 512>>>(proj_w0, proj_b0, keys0, proj_w1, proj_b1, keys1);
    router_kernel<0><<<169, 256>>>(16, 13);
    router_kernel<1><<<256, 256>>>(13, 16);
    layer0_kernel<<<BATCH * 169, 64>>>(X, w_exp0, b_exp0, w_fc0, b_fc0);
    layer1_kernel<<<BATCH * 64, 256, DYN1>>>(w_exp1, b_exp1, w_fc1, b_fc1);
    cls_kernel<<<BATCH, 128>>>(w_cls, b_cls, out);
}

// round 4
// speedup vs baseline: 1.4986x; 1.4072x over previous
#include <cuda_runtime.h>
#include <cuda_bf16.h>
#include <math.h>

// ---------------------------------------------------------------------------
// PCENetwork: patch-conditional experts, 2 layers + pool + classifier
// B=16, H=W=208
// Layer0: ps=16 (13x13=169 patches), Cin=3, E=8, Cout=8, then 1x1 fc 8->8
// Layer1: ps=13 (16x16=256 patches), Cin=8, E=8, Cout=16, then 1x1 fc 16->16
// Pool: 26x26 mean; fc1+pool fused into layer1 via per-patch channel sums
// Classifier: [16,1024] @ [100,1024]^T + b
// f32x2 packed FMA (Blackwell FFMA2) over output-channel pairs.
// ---------------------------------------------------------------------------

#define BATCH 16
#define HW 208

typedef unsigned long long u64;

__device__ float g_x1[BATCH * 8 * HW * HW];      // layer0 output (after fc0)
__device__ float g_scores0[169 * 8];
__device__ float g_scores1[256 * 8];
__device__ float g_A0[8 * 20];
__device__ float g_c0[8];
__device__ float g_A1[8 * 20];
__device__ float g_c1[8];
__device__ float g_pooled[BATCH * 16 * 8 * 8];   // [b][c][8][8]

// ---- f32x2 helpers --------------------------------------------------------
__device__ __forceinline__ u64 f2_pack(float lo, float hi) {
    u64 out; unsigned a = __float_as_uint(lo), b = __float_as_uint(hi);
    asm("mov.b64 %0, {%1, %2};" : "=l"(out) : "r"(a), "r"(b));
    return out;
}
__device__ __forceinline__ u64 f2_bcast(float t) {
    u64 out; unsigned a = __float_as_uint(t);
    asm("mov.b64 %0, {%1, %2};" : "=l"(out) : "r"(a), "r"(a));
    return out;
}
__device__ __forceinline__ u64 f2_fma(u64 a, u64 b, u64 c) {
    u64 d;
    asm("fma.rn.f32x2 %0, %1, %2, %3;" : "=l"(d) : "l"(a), "l"(b), "l"(c));
    return d;
}
__device__ __forceinline__ void f2_unpack(u64 v, float& lo, float& hi) {
    unsigned a, b;
    asm("mov.b64 {%0, %1}, %2;" : "=r"(a), "=r"(b) : "l"(v));
    lo = __uint_as_float(a); hi = __uint_as_float(b);
}

// ---------------------------------------------------------------------------
// Router prep: collapse proj(128x20) and keys(8x128) into A(8x20), c(8)
// ---------------------------------------------------------------------------
__global__ void prep_kernel(const float* __restrict__ pw0, const float* __restrict__ pb0,
                            const float* __restrict__ k0,
                            const float* __restrict__ pw1, const float* __restrict__ pb1,
                            const float* __restrict__ k1) {
    int tid = blockIdx.x * blockDim.x + threadIdx.x;
    if (tid < 160) {
        int e = tid / 20, c = tid % 20;
        float v = 0.f;
        for (int d = 0; d < 128; d++) v += k0[e * 128 + d] * pw0[d * 20 + c];
        g_A0[tid] = v;
    } else if (tid < 168) {
        int e = tid - 160;
        float v = 0.f;
        for (int d = 0; d < 128; d++) v += k0[e * 128 + d] * pb0[d];
        g_c0[e] = v;
    } else if (tid < 328) {
        int t = tid - 168;
        int e = t / 20, c = t % 20;
        float v = 0.f;
        for (int d = 0; d < 128; d++) v += k1[e * 128 + d] * pw1[d * 20 + c];
        g_A1[t] = v;
    } else if (tid < 336) {
        int e = tid - 328;
        float v = 0.f;
        for (int d = 0; d < 128; d++) v += k1[e * 128 + d] * pb1[d];
        g_c1[e] = v;
    }
}

// ---------------------------------------------------------------------------
// Router: per-patch mean of 20 Fourier channels -> logits -> softmax ->
// threshold(1/16) -> renorm.
// ---------------------------------------------------------------------------
template <int LAYER>
__global__ void router_kernel(int ps, int gw) {
    const float* A  = (LAYER == 0) ? g_A0 : g_A1;
    const float* cb = (LAYER == 0) ? g_c0 : g_c1;
    float* scores   = (LAYER == 0) ? g_scores0 : g_scores1;

    int p = blockIdx.x;
    int ph = p / gw, pw = p % gw;
    __shared__ float s_phi[20];
    int tid = threadIdx.x;
    if (tid < 20) s_phi[tid] = 0.f;
    __syncthreads();

    float loc[20];
#pragma unroll
    for (int i = 0; i < 20; i++) loc[i] = 0.f;

    const float PI = 3.14159265358979323846f;
    int n = ps * ps;
    for (int i = tid; i < n; i += blockDim.x) {
        int y = i / ps, x = i % ps;
        int gy = ph * ps + y, gx = pw * ps + x;
        float yy = (2.0f * (float)gy) / 207.0f - 1.0f;
        float xx = (2.0f * (float)gx) / 207.0f - 1.0f;
        float r = sqrtf(xx * xx + yy * yy);
        float a = atan2f(yy, xx);
        loc[0] += xx; loc[1] += yy; loc[2] += r; loc[3] += a;
        float base[4] = {xx, yy, r, a};
        int c = 4;
#pragma unroll
        for (int f = 1; f <= 2; f++) {
            float w = (f == 1 ? 2.0f : 4.0f) * PI;
#pragma unroll
            for (int bb = 0; bb < 4; bb++) {
                float sv, cv;
                sincosf(w * base[bb], &sv, &cv);
                loc[c++] += sv;
                loc[c++] += cv;
            }
        }
    }
#pragma unroll
    for (int k = 0; k < 20; k++) {
        float v = loc[k];
#pragma unroll
        for (int off = 16; off; off >>= 1) v += __shfl_down_sync(0xffffffffu, v, off);
        if ((tid & 31) == 0) atomicAdd(&s_phi[k], v);
    }
    __syncthreads();
    if (tid == 0) {
        float inv = 1.0f / (float)n;
        float logit[8];
        float mx = -1e30f;
#pragma unroll
        for (int e = 0; e < 8; e++) {
            float v = cb[e];
            for (int c = 0; c < 20; c++) v += A[e * 20 + c] * (s_phi[c] * inv);
            logit[e] = v;
            mx = fmaxf(mx, v);
        }
        float sum = 0.f;
#pragma unroll
        for (int e = 0; e < 8; e++) { logit[e] = expf(logit[e] - mx); sum += logit[e]; }
        float s2 = 0.f;
#pragma unroll
        for (int e = 0; e < 8; e++) {
            float sc = logit[e] / sum;
            sc = (sc > 0.0625f) ? sc : 0.f;
            logit[e] = sc;
            s2 += sc;
        }
        float inv2 = 1.0f / (s2 + 1e-6f);
#pragma unroll
        for (int e = 0; e < 8; e++) scores[p * 8 + e] = logit[e] * inv2;
    }
}

// ---------------------------------------------------------------------------
// Layer 0 (f32x2): block per (b,patch); 64 threads = (ocPair 0..3, row 0..15).
// Thread computes a 16-pixel row for an oc PAIR packed in f32x2.
// Weights stored as pre-paired float2 in smem. fc0 fused via smem staging.
// ---------------------------------------------------------------------------
__global__ __launch_bounds__(64) void layer0_kernel(
        const float* __restrict__ X, const float* __restrict__ w_exp,
        const float* __restrict__ b_exp, const float* __restrict__ w_fc,
        const float* __restrict__ b_fc) {
    int bp = blockIdx.x;
    int b = bp / 169, p = bp % 169;
    int ph = p / 13, pw = p % 13;

    __shared__ float2 s_w2[8 * 4 * 3 * 9];   // [e][ocq][ic][9] paired oc
    __shared__ float2 s_b2[8 * 4];           // [e][ocq]
    __shared__ float s_tile[3][18][18];
    __shared__ float s_comb[8][16][16];      // fc0 staging
    __shared__ float s_fc[64], s_bfc[8], s_sc[8];

    int tid = threadIdx.x;
    // paired weight load: w_exp[((e*8+oc)*3+ic)*9+k], oc pair stride = 27
    for (int i = tid; i < 864; i += 64) {
        int k = i % 9, t = i / 9;
        int ic = t % 3; t /= 3;
        int ocq = t & 3, e = t >> 2;
        int base = ((e * 8 + 2 * ocq) * 3 + ic) * 9 + k;
        s_w2[i] = make_float2(w_exp[base], w_exp[base + 27]);
    }
    if (tid < 32) {
        int e = tid >> 2, ocq = tid & 3;
        s_b2[tid] = make_float2(b_exp[e * 8 + 2 * ocq], b_exp[e * 8 + 2 * ocq + 1]);
    }
    if (tid < 64) s_fc[tid] = w_fc[tid];
    if (tid < 8) { s_bfc[tid] = b_fc[tid]; s_sc[tid] = g_scores0[p * 8 + tid]; }
    for (int i = tid; i < 3 * 18 * 18; i += 64) ((float*)s_tile)[i] = 0.f;
    __syncthreads();

    int y0 = ph * 16, x0 = pw * 16;
    for (int i = tid; i < 3 * 256; i += 64) {
        int c = i >> 8, r = i & 255;
        int y = r >> 4, x = r & 15;
        s_tile[c][y + 1][x + 1] = X[((b * 3 + c) * HW + y0 + y) * HW + x0 + x];
    }
    __syncthreads();

    int row = tid & 15;      // output row within patch
    int ocq = tid >> 4;      // 0..3 -> oc = 2*ocq, 2*ocq+1

    float comb0[16], comb1[16];
#pragma unroll
    for (int px = 0; px < 16; px++) { comb0[px] = 0.f; comb1[px] = 0.f; }

    for (int e = 0; e < 8; e++) {
        float s = s_sc[e];
        if (s == 0.f) continue;
        u64 acc[16];
        {
            float2 bb = s_b2[e * 4 + ocq];
            u64 bp2 = f2_pack(bb.x, bb.y);
#pragma unroll
            for (int px = 0; px < 16; px++) acc[px] = bp2;
        }
#pragma unroll
        for (int ic = 0; ic < 3; ic++) {
            const u64* wp = (const u64*)&s_w2[((e * 4 + ocq) * 3 + ic) * 9];
#pragma unroll
            for (int ky = 0; ky < 3; ky++) {
                u64 w0 = wp[ky * 3 + 0], w1 = wp[ky * 3 + 1], w2 = wp[ky * 3 + 2];
                const float* tr = &s_tile[ic][row + ky][0];
                u64 tb[18];
#pragma unroll
                for (int j = 0; j < 18; j++) tb[j] = f2_bcast(tr[j]);
#pragma unroll
                for (int px = 0; px < 16; px++) {
                    u64 v = acc[px];
                    v = f2_fma(w0, tb[px], v);
                    v = f2_fma(w1, tb[px + 1], v);
                    v = f2_fma(w2, tb[px + 2], v);
                    acc[px] = v;
                }
            }
        }
#pragma unroll
        for (int px = 0; px < 16; px++) {
            float lo, hi;
            f2_unpack(acc[px], lo, hi);
            comb0[px] += s * fmaxf(lo, 0.f);
            comb1[px] += s * fmaxf(hi, 0.f);
        }
    }

#pragma unroll
    for (int px = 0; px < 16; px++) {
        s_comb[2 * ocq + 0][row][px] = comb0[px];
        s_comb[2 * ocq + 1][row][px] = comb1[px];
    }
    __syncthreads();

    // fc0 (1x1, 8->8): thread handles 4 consecutive pixels -> float4 stores
    {
        int i0 = tid * 4;
        int y = i0 >> 4, xb = i0 & 15;
        float cv[8][4];
#pragma unroll
        for (int k = 0; k < 8; k++)
#pragma unroll
            for (int j = 0; j < 4; j++) cv[k][j] = s_comb[k][y][xb + j];
        int gy = y0 + y, gx = x0 + xb;
#pragma unroll
        for (int c = 0; c < 8; c++) {
            float4 out;
            float* po = (float*)&out;
#pragma unroll
            for (int j = 0; j < 4; j++) {
                float v = s_bfc[c];
#pragma unroll
                for (int k = 0; k < 8; k++) v += s_fc[c * 8 + k] * cv[k][j];
                po[j] = v;
            }
            *(float4*)&g_x1[((size_t)(b * 8 + c) * HW + gy) * HW + gx] = out;
        }
    }
}

// ---------------------------------------------------------------------------
// Layer 1 (f32x2) + fc1 + pool. Block per (b, patch); 128 threads,
// 104 active = (ocPair 0..7, row 0..12). Thread computes a 13-pixel row for
// an oc PAIR. Only channel SUMS are needed (fc1, pool linear over pixels).
// Per-patch sums -> fc1 -> atomicAdd into g_pooled (pool cell = 2x2 patches).
// ---------------------------------------------------------------------------
__global__ __launch_bounds__(128) void layer1_kernel(
        const float* __restrict__ w_exp, const float* __restrict__ b_exp,
        const float* __restrict__ w_fc, const float* __restrict__ b_fc) {
    __shared__ float2 s_w2[8 * 8 * 8 * 9];   // [e][ocq][ic][9] paired oc (36 KB)
    __shared__ float2 s_b2[8 * 8];           // [e][ocq]
    __shared__ float s_tile[8][15][15];      // 7.2 KB
    __shared__ float s_fc[256], s_bfc[16], s_sc[8], s_S[16];

    int bp = blockIdx.x;
    int b = bp >> 8, p = bp & 255;
    int ph = p >> 4, pw = p & 15;

    int tid = threadIdx.x;
    // paired weight load: w_exp[((e*16+oc)*8+ic)*9+k], oc pair stride = 72
    for (int i = tid; i < 4608; i += 128) {
        int k = i % 9, t = i / 9;
        int ic = t & 7; t >>= 3;
        int ocq = t & 7, e = t >> 3;
        int base = ((e * 16 + 2 * ocq) * 8 + ic) * 9 + k;
        s_w2[i] = make_float2(w_exp[base], w_exp[base + 72]);
    }
    if (tid < 64) {
        int e = tid >> 3, ocq = tid & 7;
        s_b2[tid] = make_float2(b_exp[e * 16 + 2 * ocq], b_exp[e * 16 + 2 * ocq + 1]);
    }
    for (int i = tid; i < 256; i += 128) s_fc[i] = w_fc[i];
    if (tid < 16) { s_bfc[tid] = b_fc[tid]; s_S[tid] = 0.f; }
    if (tid < 8) s_sc[tid] = g_scores1[p * 8 + tid];
    for (int i = tid; i < 8 * 15 * 15; i += 128) ((float*)s_tile)[i] = 0.f;
    __syncthreads();

    for (int i = tid; i < 8 * 169; i += 128) {
        int c = i / 169, rr = i % 169;
        int y = rr / 13, x = rr % 13;
        s_tile[c][y + 1][x + 1] =
            g_x1[((size_t)(b * 8 + c) * HW + ph * 13 + y) * HW + pw * 13 + x];
    }
    __syncthreads();

    if (tid < 104) {
        int ocq = tid / 13;    // 0..7 -> oc = 2*ocq, 2*ocq+1
        int row = tid % 13;

        float sum0 = 0.f, sum1 = 0.f;
        for (int e = 0; e < 8; e++) {
            float s = s_sc[e];
            if (s == 0.f) continue;
            u64 acc[13];
            {
                float2 bb = s_b2[e * 8 + ocq];
                u64 bp2 = f2_pack(bb.x, bb.y);
#pragma unroll
                for (int px = 0; px < 13; px++) acc[px] = bp2;
            }
#pragma unroll
            for (int ic = 0; ic < 8; ic++) {
                const u64* wp = (const u64*)&s_w2[((e * 8 + ocq) * 8 + ic) * 9];
#pragma unroll
                for (int ky = 0; ky < 3; ky++) {
                    u64 w0 = wp[ky * 3 + 0], w1 = wp[ky * 3 + 1], w2 = wp[ky * 3 + 2];
                    const float* tr = &s_tile[ic][row + ky][0];
                    u64 tb[15];
#pragma unroll
                    for (int j = 0; j < 15; j++) tb[j] = f2_bcast(tr[j]);
#pragma unroll
                    for (int px = 0; px < 13; px++) {
                        u64 v = acc[px];
                        v = f2_fma(w0, tb[px], v);
                        v = f2_fma(w1, tb[px + 1], v);
                        v = f2_fma(w2, tb[px + 2], v);
                        acc[px] = v;
                    }
                }
            }
            float rs0 = 0.f, rs1 = 0.f;
#pragma unroll
            for (int px = 0; px < 13; px++) {
                float lo, hi;
                f2_unpack(acc[px], lo, hi);
                rs0 += fmaxf(lo, 0.f);
                rs1 += fmaxf(hi, 0.f);
            }
            sum0 += s * rs0;
            sum1 += s * rs1;
        }
        atomicAdd(&s_S[2 * ocq + 0], sum0);
        atomicAdd(&s_S[2 * ocq + 1], sum1);
    }
    __syncthreads();

    // fc1 on patch channel sums, accumulate into pool cell (ph/2, pw/2)
    if (tid < 16) {
        int c = tid;
        float v = 169.0f * s_bfc[c];
#pragma unroll
        for (int k = 0; k < 16; k++) v += s_fc[c * 16 + k] * s_S[k];
        atomicAdd(&g_pooled[((b * 16 + c) * 8 + (ph >> 1)) * 8 + (pw >> 1)],
                  v * (1.0f / 676.0f));
    }
}

// ---------------------------------------------------------------------------
__global__ void zero_pooled_kernel() {
    int i = blockIdx.x * blockDim.x + threadIdx.x;
    if (i < BATCH * 16 * 64) g_pooled[i] = 0.f;
}

// ---------------------------------------------------------------------------
// Classifier: [16,1024] @ w_cls[100,1024]^T + b_cls -> [16,100]
// ---------------------------------------------------------------------------
__global__ void cls_kernel(const float* __restrict__ w, const float* __restrict__ bias,
                           float* __restrict__ out) {
    int b = blockIdx.x;
    __shared__ float s_p[1024];
    for (int i = threadIdx.x; i < 1024; i += blockDim.x) s_p[i] = g_pooled[b * 1024 + i];
    __syncthreads();
    for (int j = threadIdx.x; j < 100; j += blockDim.x) {
        float v = bias[j];
        const float* wr = &w[j * 1024];
        for (int k = 0; k < 1024; k++) v += wr[k] * s_p[k];
        out[b * 100 + j] = v;
    }
}

// ---------------------------------------------------------------------------
extern "C" void kernel_launch(void* const* d_in, const int* in_sizes, int n_in,
                              void* d_out, int out_size) {
    const float* X       = (const float*)d_in[0];
    const float* w_exp0  = (const float*)d_in[1];
    const float* b_exp0  = (const float*)d_in[2];
    const float* w_fc0   = (const float*)d_in[3];
    const float* b_fc0   = (const float*)d_in[4];
    const float* proj_w0 = (const float*)d_in[5];
    const float* proj_b0 = (const float*)d_in[6];
    const float* keys0   = (const float*)d_in[7];
    const float* w_exp1  = (const float*)d_in[8];
    const float* b_exp1  = (const float*)d_in[9];
    const float* w_fc1   = (const float*)d_in[10];
    const float* b_fc1   = (const float*)d_in[11];
    const float* proj_w1 = (const float*)d_in[12];
    const float* proj_b1 = (const float*)d_in[13];
    const float* keys1   = (const float*)d_in[14];
    const float* w_cls   = (const float*)d_in[15];
    const float* b_cls   = (const float*)d_in[16];
    float* out = (float*)d_out;

    prep_kernel<<<1, 512>>>(proj_w0, proj_b0, keys0, proj_w1, proj_b1, keys1);
    router_kernel<0><<<169, 256>>>(16, 13);
    router_kernel<1><<<256, 256>>>(13, 16);
    zero_pooled_kernel<<<(BATCH * 16 * 64 + 255) / 256, 256>>>();
    layer0_kernel<<<BATCH * 169, 64>>>(X, w_exp0, b_exp0, w_fc0, b_fc0);
    layer1_kernel<<<BATCH * 256, 128>>>(w_exp1, b_exp1, w_fc1, b_fc1);
    cls_kernel<<<BATCH, 128>>>(w_cls, b_cls, out);
}